// round 1
// baseline (speedup 1.0000x reference)
#include <cuda_runtime.h>

// Problem constants (fixed by the dataset)
#define NB   64          // batch
#define T1   4097        // maxT+1
#define MAXT 4096
#define HB   16          // hidden states
#define NA   18          // actions
#define CL   128         // chunk length (steps per chunk)
#define NC   32          // number of chunks (covers steps i = 1..4095)

// Scratch: per (batch, chunk) a normalized 16x16 transfer matrix (row-major:
// g_mats[b][ch][k][c] = P[k][c], column c scaled by exp(lam[c])) + per-column log-scales.
__device__ float g_mats[NB * NC * HB * HB];
__device__ float g_lam[NB * NC * HB];

// ---------------------------------------------------------------------------
// Chunk kernel: one warp per (batch, chunk). Lanes 0-15 own matrix columns
// (lanes 16-31 mirror the math and act as extra producers for the exp vectors).
//
// Per step i:  P <- N_i * P  where
//   (N_i * P)[k][c] = eas_k * (sum_j ebeta_j P[j][c]) + eao_k * P[k][c]
//   ebeta_j = exp(beta_j), eas_k = exp(al_k + start_k), eao_k = exp(al_k + omb_k)
// Each step the column is renormalized by s_c = sum_j ebeta_j P[j][c] and
// lam_c += log(s_c), keeping everything comfortably inside fp32 range.
// Steps with i >= lengths[b] are identity => loop simply stops at n_act.
// ---------------------------------------------------------------------------

__device__ __forceinline__ void load_group(
    int g0, int n_act, int i0, int c, int half, size_t rowbase,
    const float* __restrict__ stopl, const float* __restrict__ startl,
    const float* __restrict__ alogp, const int* __restrict__ s_act_w,
    float (&rs)[8], float (&rt)[8], float (&ra)[8])
{
#pragma unroll
    for (int u = 0; u < 8; ++u) {
        int tt = g0 + u;
        if (tt < n_act) {
            size_t i = (size_t)(i0 + tt);
            rs[u] = __ldg(stopl + (rowbase + i) * 32 + c * 2 + half);
            rt[u] = __ldg(startl + (rowbase + i) * 16 + c);
            int a = s_act_w[tt];
            ra[u] = __ldg(alogp + ((rowbase + i) * 16 + (size_t)c) * 18 + a);
        }
    }
}

__device__ __forceinline__ void consume_group(
    int g0, int n_act, int c, int half,
    float (&rs)[8], float (&rt)[8], float (&ra)[8],
    float* __restrict__ vec,   // [2][3][16] double-buffered vector store
    float (&p)[HB], float& lam)
{
#pragma unroll
    for (int u = 0; u < 8; ++u) {
        int tt = g0 + u;
        if (tt >= n_act) return;   // uniform across the warp
        float* vb = vec + (u & 1) * 48;
        if (!half) {
            vb[c]      = __expf(rs[u]);            // ebeta_c
            vb[16 + c] = __expf(ra[u] + rt[u]);    // eas_c = exp(al + start)
        } else {
            vb[32 + c] = __expf(ra[u] + rs[u]);    // eao_c = exp(al + omb)
        }
        __syncwarp();
        const float4* EB = (const float4*)(vb);
        const float4* EA = (const float4*)(vb + 16);
        const float4* EO = (const float4*)(vb + 32);
        float4 e0 = EB[0], e1 = EB[1], e2 = EB[2], e3 = EB[3];
        float t0 = e0.x * p[0]  + e0.y * p[1]  + e0.z * p[2]  + e0.w * p[3];
        float t1 = e1.x * p[4]  + e1.y * p[5]  + e1.z * p[6]  + e1.w * p[7];
        float t2 = e2.x * p[8]  + e2.y * p[9]  + e2.z * p[10] + e2.w * p[11];
        float t3 = e3.x * p[12] + e3.y * p[13] + e3.z * p[14] + e3.w * p[15];
        float s = (t0 + t1) + (t2 + t3);
        float r = __fdividef(1.0f, s);
        lam += __logf(s);
        float4 a0 = EA[0], a1 = EA[1], a2 = EA[2], a3 = EA[3];
        float4 o0 = EO[0], o1 = EO[1], o2 = EO[2], o3 = EO[3];
        p[0]  = fmaf(o0.x, p[0]  * r, a0.x);
        p[1]  = fmaf(o0.y, p[1]  * r, a0.y);
        p[2]  = fmaf(o0.z, p[2]  * r, a0.z);
        p[3]  = fmaf(o0.w, p[3]  * r, a0.w);
        p[4]  = fmaf(o1.x, p[4]  * r, a1.x);
        p[5]  = fmaf(o1.y, p[5]  * r, a1.y);
        p[6]  = fmaf(o1.z, p[6]  * r, a1.z);
        p[7]  = fmaf(o1.w, p[7]  * r, a1.w);
        p[8]  = fmaf(o2.x, p[8]  * r, a2.x);
        p[9]  = fmaf(o2.y, p[9]  * r, a2.y);
        p[10] = fmaf(o2.z, p[10] * r, a2.z);
        p[11] = fmaf(o2.w, p[11] * r, a2.w);
        p[12] = fmaf(o3.x, p[12] * r, a3.x);
        p[13] = fmaf(o3.y, p[13] * r, a3.y);
        p[14] = fmaf(o3.z, p[14] * r, a3.z);
        p[15] = fmaf(o3.w, p[15] * r, a3.w);
    }
}

__global__ __launch_bounds__(128) void hmm_chunk_kernel(
    const float* __restrict__ alogp,
    const float* __restrict__ stopl,
    const float* __restrict__ startl,
    const int* __restrict__ actions,
    const int* __restrict__ lengths)
{
    const int wib  = threadIdx.x >> 5;
    const int lane = threadIdx.x & 31;
    const int gw   = blockIdx.x * 4 + wib;
    const int b    = gw >> 5;       // 64 batches
    const int ch   = gw & 31;       // 32 chunks
    const int c    = lane & 15;
    const int half = lane >> 4;

    __shared__ int s_act[4][CL];
    __shared__ __align__(16) float s_vec[4][2][3][HB];

    const int i0    = 1 + ch * CL;
    const int count = min(CL, MAXT - i0);
    const int len   = lengths[b];
    int n_act = len - i0;
    n_act = max(0, min(n_act, count));

    for (int idx = lane; idx < n_act; idx += 32)
        s_act[wib][idx] = actions[(size_t)b * MAXT + i0 + idx];
    __syncwarp();

    float p[HB];
#pragma unroll
    for (int k = 0; k < HB; ++k) p[k] = (k == c) ? 1.0f : 0.0f;
    float lam = 0.0f;

    if (n_act > 0) {
        const size_t rowbase = (size_t)b * T1;
        float s0[8], t0r[8], a0r[8];   // bank 0
        float s1[8], t1r[8], a1r[8];   // bank 1
        float* vec = &s_vec[wib][0][0][0];
        const int* sa = &s_act[wib][0];

        load_group(0, n_act, i0, c, half, rowbase, stopl, startl, alogp, sa, s0, t0r, a0r);
        for (int g0 = 0; g0 < n_act; g0 += 16) {
            load_group(g0 + 8, n_act, i0, c, half, rowbase, stopl, startl, alogp, sa, s1, t1r, a1r);
            consume_group(g0, n_act, c, half, s0, t0r, a0r, vec, p, lam);
            if (g0 + 8 < n_act) {
                load_group(g0 + 16, n_act, i0, c, half, rowbase, stopl, startl, alogp, sa, s0, t0r, a0r);
                consume_group(g0 + 8, n_act, c, half, s1, t1r, a1r, vec, p, lam);
            }
        }
    }

    if (!half) {
        size_t mb = (size_t)(b * NC + ch) * HB * HB;
#pragma unroll
        for (int k = 0; k < HB; ++k)
            g_mats[mb + (size_t)k * HB + c] = p[k];   // store row-major (transposed for combine)
        g_lam[(size_t)(b * NC + ch) * HB + c] = lam;
    }
}

// ---------------------------------------------------------------------------
// Combine kernel: one warp per batch. f kept in log domain across chunks.
//   f_new[k] = m + log( sum_c P[k][c] * exp(f[c] + lam[c] - m) )
// Lane holds state index (lane & 15); halves are exact duplicates.
// ---------------------------------------------------------------------------
__global__ __launch_bounds__(32) void hmm_combine_kernel(
    const float* __restrict__ alogp,
    const float* __restrict__ stopl,
    const float* __restrict__ startl,
    const int* __restrict__ actions,
    const int* __restrict__ lengths,
    float* __restrict__ out)
{
    const int b = blockIdx.x;
    const int lane = threadIdx.x;
    const int c = lane & 15;
    __shared__ __align__(16) float wbuf[2][HB];

    const int len = lengths[b];
    const int a0i = actions[(size_t)b * MAXT];
    const size_t rb = (size_t)b * T1;

    float f = startl[rb * 16 + c] + alogp[(rb * 16 + (size_t)c) * 18 + a0i];

    // preload chunk 0
    float4 r0, r1, r2, r3; float lamv;
    {
        const float4* mp = (const float4*)(g_mats + ((size_t)(b * NC) * HB + c) * HB);
        r0 = mp[0]; r1 = mp[1]; r2 = mp[2]; r3 = mp[3];
        lamv = g_lam[(size_t)(b * NC) * HB + c];
    }

    for (int ch = 0; ch < NC; ++ch) {
        float4 n0 = r0, n1 = r1, n2 = r2, n3 = r3; float nlam = lamv;
        if (ch + 1 < NC) {
            const float4* mp = (const float4*)(g_mats + ((size_t)(b * NC + ch + 1) * HB + c) * HB);
            n0 = mp[0]; n1 = mp[1]; n2 = mp[2]; n3 = mp[3];
            nlam = g_lam[(size_t)(b * NC + ch + 1) * HB + c];
        }
        float t = f + lamv;
        float m = t;
        m = fmaxf(m, __shfl_xor_sync(0xffffffffu, m, 1));
        m = fmaxf(m, __shfl_xor_sync(0xffffffffu, m, 2));
        m = fmaxf(m, __shfl_xor_sync(0xffffffffu, m, 4));
        m = fmaxf(m, __shfl_xor_sync(0xffffffffu, m, 8));
        float wv = __expf(t - m);
        if (lane < 16) wbuf[ch & 1][c] = wv;
        __syncwarp();
        const float4* W = (const float4*)wbuf[ch & 1];
        float4 w0 = W[0], w1 = W[1], w2 = W[2], w3 = W[3];
        float d0 = r0.x * w0.x + r0.y * w0.y + r0.z * w0.z + r0.w * w0.w;
        float d1 = r1.x * w1.x + r1.y * w1.y + r1.z * w1.z + r1.w * w1.w;
        float d2 = r2.x * w2.x + r2.y * w2.y + r2.z * w2.z + r2.w * w2.w;
        float d3 = r3.x * w3.x + r3.y * w3.y + r3.z * w3.z + r3.w * w3.w;
        float dot = (d0 + d1) + (d2 + d3);
        f = m + __logf(dot);
        r0 = n0; r1 = n1; r2 = n2; r3 = n3; lamv = nlam;
    }

    // final: -logsumexp_k( f[k] + stop_logps[b, len, k, STOP] )
    float stT = stopl[((rb + (size_t)len) * 16 + (size_t)c) * 2];
    float t = f + stT;
    float m = t;
    m = fmaxf(m, __shfl_xor_sync(0xffffffffu, m, 1));
    m = fmaxf(m, __shfl_xor_sync(0xffffffffu, m, 2));
    m = fmaxf(m, __shfl_xor_sync(0xffffffffu, m, 4));
    m = fmaxf(m, __shfl_xor_sync(0xffffffffu, m, 8));
    float wv = __expf(t - m);
    float sum = wv;
    sum += __shfl_xor_sync(0xffffffffu, sum, 1);
    sum += __shfl_xor_sync(0xffffffffu, sum, 2);
    sum += __shfl_xor_sync(0xffffffffu, sum, 4);
    sum += __shfl_xor_sync(0xffffffffu, sum, 8);
    sum += __shfl_xor_sync(0xffffffffu, sum, 16);  // halves duplicated => 2x
    if (lane == 0) atomicAdd(out, -(m + __logf(0.5f * sum)));
}

__global__ void hmm_zero_out(float* out)
{
    if (threadIdx.x == 0 && blockIdx.x == 0) out[0] = 0.0f;
}

extern "C" void kernel_launch(void* const* d_in, const int* in_sizes, int n_in,
                              void* d_out, int out_size)
{
    const float* alogp   = (const float*)d_in[0];
    const float* stopl   = (const float*)d_in[1];
    const float* startl  = (const float*)d_in[2];
    const int*   actions = (const int*)d_in[3];
    const int*   lengths = (const int*)d_in[4];
    float* out = (float*)d_out;

    hmm_zero_out<<<1, 32>>>(out);
    hmm_chunk_kernel<<<(NB * NC) / 4, 128>>>(alogp, stopl, startl, actions, lengths);
    hmm_combine_kernel<<<NB, 32>>>(alogp, stopl, startl, actions, lengths, out);
}